// round 6
// baseline (speedup 1.0000x reference)
#include <cuda_runtime.h>
#include <cuda_fp16.h>
#include <cstdint>

#define T_TOKENS 4096
#define DM 512
#define NE 8
#define DF 2048
#define NPAIRS (T_TOKENS * 2)
#define MAX_T1 80     // >= 8192/128 + 8
#define MAX_T2 144    // >= 8192/64 + 8

// ---------------- device scratch ------------------------------------------
__device__ int   g_counts[NE];
__device__ int   g_cursor[NE];
__device__ int   g_offsets[NE + 1];
__device__ int   g_tok_e[NPAIRS];
__device__ float g_tok_g[NPAIRS];
__device__ int   g_slot[NPAIRS];
__device__ int2  g_tiles1[MAX_T1];
__device__ int2  g_tiles2[MAX_T2];
__device__ int   g_nt1, g_nt2;
__device__ __half g_xg[(size_t)NPAIRS * DM];      // 8 MiB
__device__ __half g_Y1[(size_t)NPAIRS * DF];      // 32 MiB
__device__ __half g_W1h[(size_t)NE * DM * DF];    // 16 MiB
__device__ __half g_W2h[(size_t)NE * DF * DM];    // 16 MiB
__device__ float  g_Y2[(size_t)NPAIRS * DM];      // 16 MiB

// ---------------- helpers ----------------------------------------------------
#define LDSM_X4(R, ADDR) \
    asm volatile("ldmatrix.sync.aligned.m8n8.x4.shared.b16 {%0,%1,%2,%3}, [%4];" \
        : "=r"((R)[0]), "=r"((R)[1]), "=r"((R)[2]), "=r"((R)[3]) : "r"(ADDR))

#define LDSM_X4T(R0, R1, R2, R3, ADDR) \
    asm volatile("ldmatrix.sync.aligned.m8n8.x4.trans.shared.b16 {%0,%1,%2,%3}, [%4];" \
        : "=r"(R0), "=r"(R1), "=r"(R2), "=r"(R3) : "r"(ADDR))

#define MMA_F16(C, A, B) \
    asm volatile("mma.sync.aligned.m16n8k16.row.col.f32.f16.f16.f32 " \
        "{%0,%1,%2,%3}, {%4,%5,%6,%7}, {%8,%9}, {%0,%1,%2,%3};" \
        : "+f"((C)[0]), "+f"((C)[1]), "+f"((C)[2]), "+f"((C)[3]) \
        : "r"((A)[0]), "r"((A)[1]), "r"((A)[2]), "r"((A)[3]), \
          "r"((B)[0]), "r"((B)[1]))

#define CP16(DST, SRC) \
    asm volatile("cp.async.cg.shared.global [%0], [%1], 16;" \
        :: "r"(DST), "l"(SRC))
#define CP_COMMIT() asm volatile("cp.async.commit_group;")
#define CP_WAIT(N)  asm volatile("cp.async.wait_group %0;" :: "n"(N))

// ---------------- init / gating / routing ----------------------------------
__global__ void init_kernel() {
    int i = threadIdx.x;
    if (i < NE) { g_counts[i] = 0; g_cursor[i] = 0; }
}

__global__ void gate_kernel(const float* __restrict__ x,
                            const float* __restrict__ Wg,
                            const float* __restrict__ bg) {
    __shared__ float sWg[DM * NE];
    for (int i = threadIdx.x; i < DM * NE; i += blockDim.x) sWg[i] = Wg[i];
    __syncthreads();

    int t = blockIdx.x * blockDim.x + threadIdx.x;
    if (t >= T_TOKENS) return;
    const float* xr = x + (size_t)t * DM;

    float logit[NE];
#pragma unroll
    for (int e = 0; e < NE; e++) logit[e] = bg[e];
    for (int d = 0; d < DM; d++) {
        float xv = xr[d];
#pragma unroll
        for (int e = 0; e < NE; e++)
            logit[e] = fmaf(xv, sWg[d * NE + e], logit[e]);
    }
    int i0 = 0;
#pragma unroll
    for (int e = 1; e < NE; e++) if (logit[e] > logit[i0]) i0 = e;
    int i1 = (i0 == 0) ? 1 : 0;
#pragma unroll
    for (int e = 0; e < NE; e++)
        if (e != i0 && logit[e] > logit[i1]) i1 = e;

    float g0 = 1.0f / (1.0f + expf(logit[i1] - logit[i0]));
    float g1 = 1.0f - g0;

    g_tok_e[t * 2 + 0] = i0;  g_tok_g[t * 2 + 0] = g0;
    g_tok_e[t * 2 + 1] = i1;  g_tok_g[t * 2 + 1] = g1;
    atomicAdd(&g_counts[i0], 1);
    atomicAdd(&g_counts[i1], 1);
}

// prefix sums + build exact tile tables for both GEMMs
__global__ void prefix_kernel() {
    if (threadIdx.x != 0) return;
    int acc = 0;
#pragma unroll
    for (int e = 0; e < NE; e++) { g_offsets[e] = acc; acc += g_counts[e]; }
    g_offsets[NE] = acc;

    int n1 = 0, n2 = 0;
    for (int e = 0; e < NE; e++) {
        int seg = g_counts[e];
        for (int m0 = 0; m0 < seg; m0 += 128) { int2 v; v.x = e; v.y = m0; g_tiles1[n1++] = v; }
        for (int m0 = 0; m0 < seg; m0 += 64)  { int2 v; v.x = e; v.y = m0; g_tiles2[n2++] = v; }
    }
    g_nt1 = n1;
    g_nt2 = n2;
}

// ---------------- fused scatter + gather/convert (one block per pair) -------
__global__ __launch_bounds__(128)
void scatgath_kernel(const float* __restrict__ x) {
    __shared__ int s_row;
    int p = blockIdx.x;
    if (threadIdx.x == 0) {
        int e = g_tok_e[p];
        int pos = atomicAdd(&g_cursor[e], 1);
        int row = g_offsets[e] + pos;
        g_slot[p] = row;
        s_row = row;
    }
    __syncthreads();
    int tok = p >> 1;
    float4 v = reinterpret_cast<const float4*>(x + (size_t)tok * DM)[threadIdx.x];
    __half2 a = __floats2half2_rn(v.x, v.y);
    __half2 b = __floats2half2_rn(v.z, v.w);
    uint2 o;
    o.x = *reinterpret_cast<uint32_t*>(&a);
    o.y = *reinterpret_cast<uint32_t*>(&b);
    *reinterpret_cast<uint2*>(g_xg + (size_t)s_row * DM + (size_t)threadIdx.x * 4) = o;
}

// ---------------- one-time W -> fp16 conversion (both weights, one launch) --
__global__ void convert_w_all(const float* __restrict__ W1,
                              const float* __restrict__ W2) {
    constexpr int N1 = NE * DM * DF / 4;    // float4 count of W1
    constexpr int N2 = NE * DF * DM / 4;
    int idx = blockIdx.x * blockDim.x + threadIdx.x;
    const float* src;
    __half* dst;
    int i;
    if (idx < N1) { src = W1; dst = g_W1h; i = idx; }
    else if (idx < N1 + N2) { src = W2; dst = g_W2h; i = idx - N1; }
    else return;
    float4 v = reinterpret_cast<const float4*>(src)[i];
    __half2 a = __floats2half2_rn(v.x, v.y);
    __half2 b = __floats2half2_rn(v.z, v.w);
    uint2 o;
    o.x = *reinterpret_cast<uint32_t*>(&a);
    o.y = *reinterpret_cast<uint32_t*>(&b);
    *reinterpret_cast<uint2*>(dst + (size_t)i * 4) = o;
}

// ---------------- fp16 HMMA grouped GEMM -------------------------------------
// D = A @ B.  Tile table gives (expert, m0). CTA tile M_TILE x 128, BK=32,
// 256 threads, cp.async 3-stage, 2 CTAs/SM.
// M_TILE=128: warps 4x2, warp tile 32x64.  M_TILE=64: warps 2x4, warp tile 32x32.
template<int K_TOTAL, int N_TOTAL, int M_TILE, int RELU_OUT>
__global__ __launch_bounds__(256, 2)
void moe_mma(const float* __restrict__ bias)   // [E, N_TOTAL]
{
    constexpr int NC   = K_TOTAL / 32;
    constexpr int A_SZ = M_TILE * 40;            // elems
    constexpr int B_SZ = 32 * 136;               // elems
    constexpr int BUF  = A_SZ + B_SZ;
    constexpr int MW   = M_TILE / 32;            // warps along M
    constexpr int WN   = 128 / (8 / MW);         // warp N tile (64 or 32)
    constexpr int NTF  = WN / 8;                 // n-fragments per warp (8 or 4)
    constexpr int A_IT = (M_TILE * 4) / 256;     // int4 cp.async iters (2 or 1)

    const int cnt = RELU_OUT ? g_nt1 : g_nt2;
    if (blockIdx.x >= cnt) return;
    const int2 te = RELU_OUT ? g_tiles1[blockIdx.x] : g_tiles2[blockIdx.x];
    const int e = te.x, m0 = te.y;
    const int seg_start = g_offsets[e];
    const int seg_count = g_offsets[e + 1] - seg_start;
    const int n0 = blockIdx.y * 128;

    const int tid  = threadIdx.x;
    const int lane = tid & 31;
    const int warp = tid >> 5;
    const int wm = (warp % MW) * 32;
    const int wn = (warp / MW) * WN;

    extern __shared__ __half smraw[];
    const uint32_t sbase = (uint32_t)__cvta_generic_to_shared(smraw);

    const __half* Ap = RELU_OUT ? g_xg : g_Y1;
    const __half* Bp = (RELU_OUT ? g_W1h : g_W2h)
                       + (size_t)e * K_TOTAL * N_TOTAL + n0;

    // ---- per-thread cp.async mappings ----
    uint32_t a_soff[A_IT];
    size_t   a_gidx[A_IT];
#pragma unroll
    for (int it = 0; it < A_IT; it++) {
        int u = tid + it * 256;                  // M_TILE*4 int4 per A tile
        int r = m0 + (u >> 2);
        if (r >= seg_count) r = seg_count - 1;
        a_soff[it] = (uint32_t)((u >> 2) * 40 + (u & 3) * 8) * 2;
        a_gidx[it] = (size_t)(seg_start + r) * K_TOTAL + (u & 3) * 8;
    }
    uint32_t b_soff[2];
    size_t   b_gidx[2];
#pragma unroll
    for (int it = 0; it < 2; it++) {
        int v = tid + it * 256;                  // 512 int4 for B
        int bk = v >> 4, bn = (v & 15) * 8;
        b_soff[it] = (uint32_t)(A_SZ + bk * 136 + bn) * 2;
        b_gidx[it] = (size_t)bk * N_TOTAL + bn;
    }

    const uint32_t aoff = (uint32_t)((wm + (lane & 15)) * 40 + (lane >> 4) * 8);
    const uint32_t boff = (uint32_t)((((lane >> 3) & 1) * 8 + (lane & 7)) * 136
                                     + wn + (lane >> 4) * 8);

    float c[2 * NTF][4];
#pragma unroll
    for (int f = 0; f < 2 * NTF; f++)
#pragma unroll
        for (int q = 0; q < 4; q++) c[f][q] = 0.0f;

#define ISSUE(KC, BS) do { \
    uint32_t base_ = sbase + (uint32_t)(BS) * (BUF * 2); \
    _Pragma("unroll") \
    for (int it = 0; it < A_IT; it++) \
        CP16(base_ + a_soff[it], Ap + a_gidx[it] + (size_t)(KC) * 32); \
    _Pragma("unroll") \
    for (int it = 0; it < 2; it++) \
        CP16(base_ + b_soff[it], Bp + b_gidx[it] + (size_t)(KC) * 32 * N_TOTAL); \
} while (0)

#define COMPUTE(BS) do { \
    uint32_t base_ = sbase + (uint32_t)(BS) * (BUF * 2); \
    _Pragma("unroll") \
    for (int kt = 0; kt < 2; kt++) { \
        uint32_t ah[2][4]; \
        _Pragma("unroll") \
        for (int mt = 0; mt < 2; mt++) { \
            uint32_t ad = base_ + 2u * (aoff + (uint32_t)(mt * 640 + kt * 16)); \
            LDSM_X4(ah[mt], ad); \
        } \
        uint32_t bh[NTF][2]; \
        _Pragma("unroll") \
        for (int bt = 0; bt < NTF / 2; bt++) { \
            uint32_t bd = base_ + 2u * ((uint32_t)A_SZ + boff \
                                        + (uint32_t)(bt * 16 + kt * 16 * 136)); \
            LDSM_X4T(bh[bt * 2][0], bh[bt * 2][1], bh[bt * 2 + 1][0], bh[bt * 2 + 1][1], bd); \
        } \
        _Pragma("unroll") \
        for (int mt = 0; mt < 2; mt++) { \
            _Pragma("unroll") \
            for (int nt = 0; nt < NTF; nt++) \
                MMA_F16(c[mt * NTF + nt], ah[mt], bh[nt]); \
        } \
    } \
} while (0)

    // ---- 3-stage cp.async pipeline ----
    ISSUE(0, 0); CP_COMMIT();
    ISSUE(1, 1); CP_COMMIT();
    int cur = 0, pre = 2;
    for (int kc = 0; kc < NC; kc++) {
        if (kc + 1 < NC) { CP_WAIT(1); } else { CP_WAIT(0); }
        __syncthreads();
        if (kc + 2 < NC) { ISSUE(kc + 2, pre); CP_COMMIT(); }
        COMPUTE(cur);
        cur = (cur == 2) ? 0 : cur + 1;
        pre = (pre == 2) ? 0 : pre + 1;
    }

#undef ISSUE
#undef COMPUTE

    // ---- epilogue ----
    const float* bp = bias + (size_t)e * N_TOTAL + n0;
    const int rbase = m0 + wm + (lane >> 2);
#pragma unroll
    for (int mt = 0; mt < 2; mt++) {
#pragma unroll
        for (int nt = 0; nt < NTF; nt++) {
            float* cc = c[mt * NTF + nt];
            int col = wn + nt * 8 + 2 * (lane & 3);
            float2 bb = *reinterpret_cast<const float2*>(bp + col);
#pragma unroll
            for (int h = 0; h < 2; h++) {
                int r = rbase + mt * 16 + h * 8;
                if (r < seg_count) {
                    float v0 = cc[h * 2 + 0] + bb.x;
                    float v1 = cc[h * 2 + 1] + bb.y;
                    size_t off = (size_t)(seg_start + r) * N_TOTAL + n0 + col;
                    if (RELU_OUT) {
                        v0 = fmaxf(v0, 0.0f);
                        v1 = fmaxf(v1, 0.0f);
                        __half2 hv = __floats2half2_rn(v0, v1);
                        *reinterpret_cast<uint32_t*>(g_Y1 + off) =
                            *reinterpret_cast<uint32_t*>(&hv);
                    } else {
                        float2 o; o.x = v0; o.y = v1;
                        *reinterpret_cast<float2*>(g_Y2 + off) = o;
                    }
                }
            }
        }
    }
}

// ---------------- combine ----------------------------------------------------
__global__ void combine_kernel(float* __restrict__ out) {
    int idx = blockIdx.x * blockDim.x + threadIdx.x;
    const int vec_per_row = DM / 4;
    int t = idx / vec_per_row;
    int c = idx - t * vec_per_row;
    if (t >= T_TOKENS) return;
    int r0 = g_slot[t * 2], r1 = g_slot[t * 2 + 1];
    float g0 = g_tok_g[t * 2], g1 = g_tok_g[t * 2 + 1];
    float4 y0 = reinterpret_cast<const float4*>(g_Y2 + (size_t)r0 * DM)[c];
    float4 y1 = reinterpret_cast<const float4*>(g_Y2 + (size_t)r1 * DM)[c];
    float4 o;
    o.x = fmaf(g0, y0.x, g1 * y1.x);
    o.y = fmaf(g0, y0.y, g1 * y1.y);
    o.z = fmaf(g0, y0.z, g1 * y1.z);
    o.w = fmaf(g0, y0.w, g1 * y1.w);
    reinterpret_cast<float4*>(out)[idx] = o;
}

// ---------------- launch ------------------------------------------------------
extern "C" void kernel_launch(void* const* d_in, const int* in_sizes, int n_in,
                              void* d_out, int out_size) {
    const float* x  = (const float*)d_in[0];
    const float* Wg = (const float*)d_in[1];
    const float* bg = (const float*)d_in[2];
    const float* W1 = (const float*)d_in[3];
    const float* b1 = (const float*)d_in[4];
    const float* W2 = (const float*)d_in[5];
    const float* b2 = (const float*)d_in[6];
    float* out = (float*)d_out;

    constexpr int SMEM1 = 3 * (128 * 40 + 32 * 136) * 2;  // 56832
    constexpr int SMEM2 = 3 * (64 * 40 + 32 * 136) * 2;   // 41472
    cudaFuncSetAttribute(moe_mma<DM, DF, 128, 1>,
                         cudaFuncAttributeMaxDynamicSharedMemorySize, SMEM1);
    cudaFuncSetAttribute(moe_mma<DF, DM, 64, 0>,
                         cudaFuncAttributeMaxDynamicSharedMemorySize, SMEM2);

    init_kernel<<<1, 32>>>();
    gate_kernel<<<T_TOKENS / 128, 128>>>(x, Wg, bg);
    prefix_kernel<<<1, 32>>>();
    scatgath_kernel<<<NPAIRS, 128>>>(x);
    constexpr int WTOT = (NE * DM * DF + NE * DF * DM) / 4;
    convert_w_all<<<(WTOT + 255) / 256, 256>>>(W1, W2);

    dim3 grid1(72, DF / 128);    // exact tile table, M=128
    moe_mma<DM, DF, 128, 1><<<grid1, 256, SMEM1>>>(b1);

    dim3 grid2(136, DM / 128);   // exact tile table, M=64
    moe_mma<DF, DM, 64, 0><<<grid2, 256, SMEM2>>>(b2);

    combine_kernel<<<(T_TOKENS * DM / 4 + 255) / 256, 256>>>(out);
}

// round 7
// speedup vs baseline: 1.3307x; 1.3307x over previous
#include <cuda_runtime.h>
#include <cuda_fp16.h>
#include <cstdint>

#define T_TOKENS 4096
#define DM 512
#define NE 8
#define DF 2048
#define NPAIRS (T_TOKENS * 2)
#define MAX_T 80      // >= 8192/128 + 8

// ---------------- device scratch ------------------------------------------
__device__ int   g_counts[NE];
__device__ int   g_cursor[NE];
__device__ int   g_offsets[NE + 1];
__device__ int   g_tok_e[NPAIRS];
__device__ float g_tok_g[NPAIRS];
__device__ int   g_row_tok[NPAIRS];
__device__ float g_row_gate[NPAIRS];
__device__ int2  g_tiles[MAX_T];
__device__ int   g_nt;
__device__ __half g_xg[(size_t)NPAIRS * DM];      // 8 MiB
__device__ __half g_Y1[(size_t)NPAIRS * DF];      // 32 MiB
__device__ __half g_W1h[(size_t)NE * DM * DF];    // 16 MiB
__device__ __half g_W2h[(size_t)NE * DF * DM];    // 16 MiB

// ---------------- helpers ----------------------------------------------------
#define LDSM_X4(R, ADDR) \
    asm volatile("ldmatrix.sync.aligned.m8n8.x4.shared.b16 {%0,%1,%2,%3}, [%4];" \
        : "=r"((R)[0]), "=r"((R)[1]), "=r"((R)[2]), "=r"((R)[3]) : "r"(ADDR))

#define LDSM_X4T(R0, R1, R2, R3, ADDR) \
    asm volatile("ldmatrix.sync.aligned.m8n8.x4.trans.shared.b16 {%0,%1,%2,%3}, [%4];" \
        : "=r"(R0), "=r"(R1), "=r"(R2), "=r"(R3) : "r"(ADDR))

#define MMA_F16(C, A, B) \
    asm volatile("mma.sync.aligned.m16n8k16.row.col.f32.f16.f16.f32 " \
        "{%0,%1,%2,%3}, {%4,%5,%6,%7}, {%8,%9}, {%0,%1,%2,%3};" \
        : "+f"((C)[0]), "+f"((C)[1]), "+f"((C)[2]), "+f"((C)[3]) \
        : "r"((A)[0]), "r"((A)[1]), "r"((A)[2]), "r"((A)[3]), \
          "r"((B)[0]), "r"((B)[1]))

#define CP16(DST, SRC) \
    asm volatile("cp.async.cg.shared.global [%0], [%1], 16;" \
        :: "r"(DST), "l"(SRC))
#define CP_COMMIT() asm volatile("cp.async.commit_group;")
#define CP_WAIT(N)  asm volatile("cp.async.wait_group %0;" :: "n"(N))

// ---------------- init ------------------------------------------------------
__global__ void init_kernel() {
    int i = threadIdx.x;
    if (i < NE) { g_counts[i] = 0; g_cursor[i] = 0; }
}

// ---------------- gating: warp per token, conflict-free ---------------------
__global__ __launch_bounds__(256)
void gate_kernel(const float* __restrict__ x,
                 const float* __restrict__ Wg,
                 const float* __restrict__ bg) {
    __shared__ float sWgT[NE * DM];   // transposed [e][d], 16 KB
    for (int i = threadIdx.x; i < DM * NE; i += blockDim.x) {
        int d = i >> 3, e = i & 7;
        sWgT[e * DM + d] = Wg[i];
    }
    __syncthreads();

    int warp = threadIdx.x >> 5, lane = threadIdx.x & 31;
    int t = blockIdx.x * 8 + warp;
    const float* xr = x + (size_t)t * DM;

    float lg[NE];
#pragma unroll
    for (int e = 0; e < NE; e++) lg[e] = 0.0f;
#pragma unroll
    for (int i = 0; i < DM / 32; i++) {
        int d = lane + 32 * i;
        float xv = xr[d];                 // coalesced
#pragma unroll
        for (int e = 0; e < NE; e++)
            lg[e] = fmaf(xv, sWgT[e * DM + d], lg[e]);  // bank = lane, no conflicts
    }
#pragma unroll
    for (int off = 16; off > 0; off >>= 1)
#pragma unroll
        for (int e = 0; e < NE; e++)
            lg[e] += __shfl_xor_sync(0xFFFFFFFFu, lg[e], off);

    if (lane == 0) {
#pragma unroll
        for (int e = 0; e < NE; e++) lg[e] += bg[e];
        int i0 = 0;
#pragma unroll
        for (int e = 1; e < NE; e++) if (lg[e] > lg[i0]) i0 = e;
        int i1 = (i0 == 0) ? 1 : 0;
#pragma unroll
        for (int e = 0; e < NE; e++)
            if (e != i0 && lg[e] > lg[i1]) i1 = e;
        float g0 = 1.0f / (1.0f + expf(lg[i1] - lg[i0]));
        float g1 = 1.0f - g0;
        g_tok_e[t * 2 + 0] = i0;  g_tok_g[t * 2 + 0] = g0;
        g_tok_e[t * 2 + 1] = i1;  g_tok_g[t * 2 + 1] = g1;
        atomicAdd(&g_counts[i0], 1);
        atomicAdd(&g_counts[i1], 1);
    }
}

// prefix sums + exact M=128 tile table
__global__ void prefix_kernel() {
    if (threadIdx.x != 0) return;
    int acc = 0;
#pragma unroll
    for (int e = 0; e < NE; e++) { g_offsets[e] = acc; acc += g_counts[e]; }
    g_offsets[NE] = acc;
    int n = 0;
    for (int e = 0; e < NE; e++)
        for (int m0 = 0; m0 < g_counts[e]; m0 += 128) {
            int2 v; v.x = e; v.y = m0; g_tiles[n++] = v;
        }
    g_nt = n;
}

// ---------------- fused scatter + gather/convert (one block per pair) -------
__global__ __launch_bounds__(128)
void scatgath_kernel(const float* __restrict__ x) {
    __shared__ int s_row;
    int p = blockIdx.x;
    if (threadIdx.x == 0) {
        int e = g_tok_e[p];
        int pos = atomicAdd(&g_cursor[e], 1);
        int row = g_offsets[e] + pos;
        g_row_tok[row]  = p >> 1;
        g_row_gate[row] = g_tok_g[p];
        s_row = row;
    }
    __syncthreads();
    int tok = p >> 1;
    float4 v = reinterpret_cast<const float4*>(x + (size_t)tok * DM)[threadIdx.x];
    __half2 a = __floats2half2_rn(v.x, v.y);
    __half2 b = __floats2half2_rn(v.z, v.w);
    uint2 o;
    o.x = *reinterpret_cast<uint32_t*>(&a);
    o.y = *reinterpret_cast<uint32_t*>(&b);
    *reinterpret_cast<uint2*>(g_xg + (size_t)s_row * DM + (size_t)threadIdx.x * 4) = o;
}

// ---------------- one-time W -> fp16 conversion ------------------------------
__global__ void convert_w_all(const float* __restrict__ W1,
                              const float* __restrict__ W2) {
    constexpr int N1 = NE * DM * DF / 4;
    constexpr int N2 = NE * DF * DM / 4;
    int idx = blockIdx.x * blockDim.x + threadIdx.x;
    const float* src;
    __half* dst;
    int i;
    if (idx < N1) { src = W1; dst = g_W1h; i = idx; }
    else if (idx < N1 + N2) { src = W2; dst = g_W2h; i = idx - N1; }
    else return;
    float4 v = reinterpret_cast<const float4*>(src)[i];
    __half2 a = __floats2half2_rn(v.x, v.y);
    __half2 b = __floats2half2_rn(v.z, v.w);
    uint2 o;
    o.x = *reinterpret_cast<uint32_t*>(&a);
    o.y = *reinterpret_cast<uint32_t*>(&b);
    *reinterpret_cast<uint2*>(dst + (size_t)i * 4) = o;
}

// ---------------- fp16 HMMA grouped GEMM -------------------------------------
// CTA tile 128x128, BK=32, 256 threads, warp tile 32x64, cp.async 4-stage,
// 2 CTAs/SM.  RELU_OUT=1: Y1 = relu(x@W1+b1) fp16.
// RELU_OUT=0: out[token] += gate * (Y1@W2 + b2)  via atomicAdd (fused combine).
template<int K_TOTAL, int N_TOTAL, int RELU_OUT>
__global__ __launch_bounds__(256, 2)
void moe_mma(const float* __restrict__ bias, float* __restrict__ out)
{
    constexpr int NC   = K_TOTAL / 32;
    constexpr int A_SZ = 128 * 40;               // elems
    constexpr int B_SZ = 32 * 136;               // elems
    constexpr int BUF  = A_SZ + B_SZ;            // 9472 elems

    if (blockIdx.x >= g_nt) return;
    const int2 te = g_tiles[blockIdx.x];
    const int e = te.x, m0 = te.y;
    const int seg_start = g_offsets[e];
    const int seg_count = g_offsets[e + 1] - seg_start;
    const int n0 = blockIdx.y * 128;

    const int tid  = threadIdx.x;
    const int lane = tid & 31;
    const int warp = tid >> 5;
    const int wm = (warp & 3) * 32;
    const int wn = (warp >> 2) * 64;

    extern __shared__ __half smraw[];
    const uint32_t sbase = (uint32_t)__cvta_generic_to_shared(smraw);

    const __half* Ap = RELU_OUT ? g_xg : g_Y1;
    const __half* Bp = (RELU_OUT ? g_W1h : g_W2h)
                       + (size_t)e * K_TOTAL * N_TOTAL + n0;

    uint32_t a_soff[2];
    size_t   a_gidx[2];
#pragma unroll
    for (int it = 0; it < 2; it++) {
        int u = tid + it * 256;                  // 512 int4 per A tile
        int r = m0 + (u >> 2);
        if (r >= seg_count) r = seg_count - 1;
        a_soff[it] = (uint32_t)((u >> 2) * 40 + (u & 3) * 8) * 2;
        a_gidx[it] = (size_t)(seg_start + r) * K_TOTAL + (u & 3) * 8;
    }
    uint32_t b_soff[2];
    size_t   b_gidx[2];
#pragma unroll
    for (int it = 0; it < 2; it++) {
        int v = tid + it * 256;                  // 512 int4 for B
        int bk = v >> 4, bn = (v & 15) * 8;
        b_soff[it] = (uint32_t)(A_SZ + bk * 136 + bn) * 2;
        b_gidx[it] = (size_t)bk * N_TOTAL + bn;
    }

    const uint32_t aoff = (uint32_t)((wm + (lane & 15)) * 40 + (lane >> 4) * 8);
    const uint32_t boff = (uint32_t)((((lane >> 3) & 1) * 8 + (lane & 7)) * 136
                                     + wn + (lane >> 4) * 8);

    float c[16][4];
#pragma unroll
    for (int f = 0; f < 16; f++)
#pragma unroll
        for (int q = 0; q < 4; q++) c[f][q] = 0.0f;

#define ISSUE(KC, BS) do { \
    uint32_t base_ = sbase + (uint32_t)(BS) * (BUF * 2); \
    _Pragma("unroll") \
    for (int it = 0; it < 2; it++) \
        CP16(base_ + a_soff[it], Ap + a_gidx[it] + (size_t)(KC) * 32); \
    _Pragma("unroll") \
    for (int it = 0; it < 2; it++) \
        CP16(base_ + b_soff[it], Bp + b_gidx[it] + (size_t)(KC) * 32 * N_TOTAL); \
} while (0)

#define COMPUTE(BS) do { \
    uint32_t base_ = sbase + (uint32_t)(BS) * (BUF * 2); \
    _Pragma("unroll") \
    for (int kt = 0; kt < 2; kt++) { \
        uint32_t ah[2][4]; \
        _Pragma("unroll") \
        for (int mt = 0; mt < 2; mt++) { \
            uint32_t ad = base_ + 2u * (aoff + (uint32_t)(mt * 640 + kt * 16)); \
            LDSM_X4(ah[mt], ad); \
        } \
        uint32_t bh[8][2]; \
        _Pragma("unroll") \
        for (int bt = 0; bt < 4; bt++) { \
            uint32_t bd = base_ + 2u * ((uint32_t)A_SZ + boff \
                                        + (uint32_t)(bt * 16 + kt * 16 * 136)); \
            LDSM_X4T(bh[bt * 2][0], bh[bt * 2][1], bh[bt * 2 + 1][0], bh[bt * 2 + 1][1], bd); \
        } \
        _Pragma("unroll") \
        for (int mt = 0; mt < 2; mt++) { \
            _Pragma("unroll") \
            for (int nt = 0; nt < 8; nt++) \
                MMA_F16(c[mt * 8 + nt], ah[mt], bh[nt]); \
        } \
    } \
} while (0)

    // ---- 4-stage cp.async pipeline ----
    ISSUE(0, 0); CP_COMMIT();
    ISSUE(1, 1); CP_COMMIT();
    ISSUE(2, 2); CP_COMMIT();
    for (int kc = 0; kc < NC; kc++) {
        if (kc < NC - 2)      { CP_WAIT(2); }
        else if (kc == NC - 2){ CP_WAIT(1); }
        else                  { CP_WAIT(0); }
        __syncthreads();
        if (kc + 3 < NC) { ISSUE(kc + 3, (kc + 3) & 3); CP_COMMIT(); }
        COMPUTE(kc & 3);
    }

#undef ISSUE
#undef COMPUTE

    // ---- epilogue ----
    const float* bp = bias + (size_t)e * N_TOTAL + n0;
    const int rbase = m0 + wm + (lane >> 2);
#pragma unroll
    for (int mt = 0; mt < 2; mt++) {
#pragma unroll
        for (int nt = 0; nt < 8; nt++) {
            float* cc = c[mt * 8 + nt];
            int col = wn + nt * 8 + 2 * (lane & 3);
            float2 bb = *reinterpret_cast<const float2*>(bp + col);
#pragma unroll
            for (int h = 0; h < 2; h++) {
                int r = rbase + mt * 16 + h * 8;
                if (r < seg_count) {
                    float v0 = cc[h * 2 + 0] + bb.x;
                    float v1 = cc[h * 2 + 1] + bb.y;
                    if (RELU_OUT) {
                        v0 = fmaxf(v0, 0.0f);
                        v1 = fmaxf(v1, 0.0f);
                        __half2 hv = __floats2half2_rn(v0, v1);
                        size_t off = (size_t)(seg_start + r) * N_TOTAL + n0 + col;
                        *reinterpret_cast<uint32_t*>(g_Y1 + off) =
                            *reinterpret_cast<uint32_t*>(&hv);
                    } else {
                        int grow = seg_start + r;
                        int tok  = g_row_tok[grow];
                        float gg = g_row_gate[grow];
                        float* po = out + (size_t)tok * DM + n0 + col;
                        atomicAdd(po,     gg * v0);
                        atomicAdd(po + 1, gg * v1);
                    }
                }
            }
        }
    }
}

// ---------------- launch ------------------------------------------------------
extern "C" void kernel_launch(void* const* d_in, const int* in_sizes, int n_in,
                              void* d_out, int out_size) {
    const float* x  = (const float*)d_in[0];
    const float* Wg = (const float*)d_in[1];
    const float* bg = (const float*)d_in[2];
    const float* W1 = (const float*)d_in[3];
    const float* b1 = (const float*)d_in[4];
    const float* W2 = (const float*)d_in[5];
    const float* b2 = (const float*)d_in[6];
    float* out = (float*)d_out;

    constexpr int SMEM = 4 * (128 * 40 + 32 * 136) * 2;   // 75776
    cudaFuncSetAttribute(moe_mma<DM, DF, 1>,
                         cudaFuncAttributeMaxDynamicSharedMemorySize, SMEM);
    cudaFuncSetAttribute(moe_mma<DF, DM, 0>,
                         cudaFuncAttributeMaxDynamicSharedMemorySize, SMEM);

    cudaMemsetAsync(d_out, 0, (size_t)out_size * sizeof(float));
    init_kernel<<<1, 32>>>();
    gate_kernel<<<T_TOKENS / 8, 256>>>(x, Wg, bg);
    prefix_kernel<<<1, 32>>>();
    scatgath_kernel<<<NPAIRS, 128>>>(x);
    constexpr int WTOT = (NE * DM * DF + NE * DF * DM) / 4;
    convert_w_all<<<(WTOT + 255) / 256, 256>>>(W1, W2);

    dim3 grid1(72, DF / 128);    // exact tile table, M=128
    moe_mma<DM, DF, 1><<<grid1, 256, SMEM>>>(b1, out);

    dim3 grid2(72, DM / 128);    // same table, fused combine epilogue
    moe_mma<DF, DM, 0><<<grid2, 256, SMEM>>>(b2, out);
}